// round 11
// baseline (speedup 1.0000x reference)
#include <cuda_runtime.h>
#include <cuda_bf16.h>
#include <cstdint>

#define NPTS 16384
#define FD   512
#define MD   128
#define BM   64
#define BN   64
#define NKV  (NPTS / BN)

// smem byte offsets (all 16B aligned)
#define OFF_Q    0                 // 64 rows x 272B
#define OFF_K    17408             // 2 buffers x 17408
#define OFF_V    52224             // 2 buffers x 66560
#define OFF_P    185344            // CTA-wide P: 64 rows x 144B = 9216
#define OFF_CROW 194560            // 64 floats
#define OFF_MP   194816            // 4 pairs x 128B
#define OFF_SP   195328            // 4 pairs x 128B
#define OFF_LR   195840            // 64 floats
#define SMEM_TOTAL 196096
#define KBUF 17408
#define VBUF 66560

// Scratch (device globals: allocation-free rule)
__device__ __nv_bfloat16 g_Qb[NPTS * MD];
__device__ __nv_bfloat16 g_Kb[NPTS * MD];
__device__ __nv_bfloat16 g_Vb[NPTS * FD];
__device__ float g_att[NPTS * FD];

// ---------------------------------------------------------------------------
// helpers
// ---------------------------------------------------------------------------
__device__ __forceinline__ float cvt_tf32(float x) {
    unsigned u;
    asm("cvt.rna.tf32.f32 %0, %1;" : "=r"(u) : "f"(x));
    return __uint_as_float(u);
}
__device__ __forceinline__ unsigned fu(float x) { return __float_as_uint(x); }
__device__ __forceinline__ float ex2(float x) {
    float y;
    asm("ex2.approx.f32 %0, %1;" : "=f"(y) : "f"(x));
    return y;
}

__device__ __forceinline__ void ldsm4(unsigned* r, uint32_t a) {
    asm volatile("ldmatrix.sync.aligned.m8n8.x4.shared.b16 {%0,%1,%2,%3}, [%4];"
                 : "=r"(r[0]), "=r"(r[1]), "=r"(r[2]), "=r"(r[3]) : "r"(a));
}
__device__ __forceinline__ void ldsm4t(unsigned* r, uint32_t a) {
    asm volatile("ldmatrix.sync.aligned.m8n8.x4.trans.shared.b16 {%0,%1,%2,%3}, [%4];"
                 : "=r"(r[0]), "=r"(r[1]), "=r"(r[2]), "=r"(r[3]) : "r"(a));
}

// bf16 m16n8k16, fp32 accum
__device__ __forceinline__ void mma16(float* d, const unsigned* a, const unsigned* b) {
    asm volatile(
        "mma.sync.aligned.m16n8k16.row.col.f32.bf16.bf16.f32 "
        "{%0,%1,%2,%3}, {%4,%5,%6,%7}, {%8,%9}, {%0,%1,%2,%3};"
        : "+f"(d[0]), "+f"(d[1]), "+f"(d[2]), "+f"(d[3])
        : "r"(a[0]), "r"(a[1]), "r"(a[2]), "r"(a[3]), "r"(b[0]), "r"(b[1]));
}
// tf32 m16n8k8 (projection GEMMs)
__device__ __forceinline__ void mma8(float* d, const unsigned* a, const unsigned* b) {
    asm volatile(
        "mma.sync.aligned.m16n8k8.row.col.f32.tf32.tf32.f32 "
        "{%0,%1,%2,%3}, {%4,%5,%6,%7}, {%8,%9}, {%0,%1,%2,%3};"
        : "+f"(d[0]), "+f"(d[1]), "+f"(d[2]), "+f"(d[3])
        : "r"(a[0]), "r"(a[1]), "r"(a[2]), "r"(a[3]), "r"(b[0]), "r"(b[1]));
}

__device__ __forceinline__ void cpa16(uint32_t dst, const void* src) {
    asm volatile("cp.async.cg.shared.global [%0], [%1], 16;" :: "r"(dst), "l"(src));
}
__device__ __forceinline__ void cp_commit() {
    asm volatile("cp.async.commit_group;");
}
__device__ __forceinline__ void cp_wait0() {
    asm volatile("cp.async.wait_group 0;");
}
__device__ __forceinline__ void pair_bar(int id) {
    asm volatile("bar.sync %0, 64;" :: "r"(id) : "memory");
}

// ---------------------------------------------------------------------------
// TF32 GEMM: C[128x128 tile] = A @ B + bias. OUT_BF16 selects output type.
// ---------------------------------------------------------------------------
#define AS_STRIDE 36
#define BS_STRIDE 136
template <int OUT_BF16>
__global__ __launch_bounds__(256) void gemm_tf32_kernel(
    const float* __restrict__ A, const float* __restrict__ B,
    const float* __restrict__ bias, void* __restrict__ Cv,
    int Kd, int Nc)
{
    __shared__ float As[128 * AS_STRIDE];
    __shared__ float Bs[32 * BS_STRIDE];

    const int tid  = threadIdx.x;
    const int w    = tid >> 5;
    const int lane = tid & 31;
    const int g    = lane >> 2;
    const int t    = lane & 3;
    const int wm   = w & 3;
    const int wn   = w >> 2;
    const int rowBase = blockIdx.y * 128;
    const int colBase = blockIdx.x * 128;

    float acc[2][8][4];
#pragma unroll
    for (int mt = 0; mt < 2; mt++)
#pragma unroll
        for (int nt = 0; nt < 8; nt++)
#pragma unroll
            for (int e = 0; e < 4; e++) acc[mt][nt][e] = 0.f;

    for (int k0 = 0; k0 < Kd; k0 += 32) {
        float4 areg[4], breg[4];
#pragma unroll
        for (int e = 0; e < 4; e++) {
            int f4 = tid + 256 * e;
            int ar = f4 >> 3, ac4 = f4 & 7;
            areg[e] = *(const float4*)(A + (size_t)(rowBase + ar) * Kd + k0 + ac4 * 4);
            int br = f4 >> 5, bc4 = f4 & 31;
            breg[e] = *(const float4*)(B + (size_t)(k0 + br) * Nc + colBase + bc4 * 4);
        }
        __syncthreads();
#pragma unroll
        for (int e = 0; e < 4; e++) {
            int f4 = tid + 256 * e;
            int ar = f4 >> 3, ac4 = f4 & 7;
            float4 v = areg[e];
            v.x = cvt_tf32(v.x); v.y = cvt_tf32(v.y);
            v.z = cvt_tf32(v.z); v.w = cvt_tf32(v.w);
            *(float4*)(As + ar * AS_STRIDE + ac4 * 4) = v;
            int br = f4 >> 5, bc4 = f4 & 31;
            float4 u = breg[e];
            u.x = cvt_tf32(u.x); u.y = cvt_tf32(u.y);
            u.z = cvt_tf32(u.z); u.w = cvt_tf32(u.w);
            *(float4*)(Bs + br * BS_STRIDE + bc4 * 4) = u;
        }
        __syncthreads();

#pragma unroll
        for (int kt = 0; kt < 4; kt++) {
            unsigned afr[2][4];
#pragma unroll
            for (int mt = 0; mt < 2; mt++) {
                const float* ap = As + (wm * 32 + mt * 16) * AS_STRIDE + kt * 8;
                afr[mt][0] = fu(ap[g * AS_STRIDE + t]);
                afr[mt][1] = fu(ap[(g + 8) * AS_STRIDE + t]);
                afr[mt][2] = fu(ap[g * AS_STRIDE + t + 4]);
                afr[mt][3] = fu(ap[(g + 8) * AS_STRIDE + t + 4]);
            }
#pragma unroll
            for (int nt = 0; nt < 8; nt++) {
                const float* bp = Bs + wn * 64 + nt * 8;
                unsigned bfr[2];
                bfr[0] = fu(bp[(kt * 8 + t) * BS_STRIDE + g]);
                bfr[1] = fu(bp[(kt * 8 + t + 4) * BS_STRIDE + g]);
#pragma unroll
                for (int mt = 0; mt < 2; mt++) mma8(acc[mt][nt], afr[mt], bfr);
            }
        }
    }

#pragma unroll
    for (int mt = 0; mt < 2; mt++) {
        int r0 = rowBase + wm * 32 + mt * 16;
#pragma unroll
        for (int nt = 0; nt < 8; nt++) {
            int col = colBase + wn * 64 + nt * 8 + 2 * t;
            float b0 = bias[col], b1 = bias[col + 1];
            if (OUT_BF16) {
                __nv_bfloat16* C = (__nv_bfloat16*)Cv;
                __nv_bfloat162 lo = __float22bfloat162_rn(
                    make_float2(acc[mt][nt][0] + b0, acc[mt][nt][1] + b1));
                __nv_bfloat162 hi = __float22bfloat162_rn(
                    make_float2(acc[mt][nt][2] + b0, acc[mt][nt][3] + b1));
                *(__nv_bfloat162*)(C + (size_t)(r0 + g)     * Nc + col) = lo;
                *(__nv_bfloat162*)(C + (size_t)(r0 + g + 8) * Nc + col) = hi;
            } else {
                float* C = (float*)Cv;
                *(float2*)(C + (size_t)(r0 + g) * Nc + col) =
                    make_float2(acc[mt][nt][0] + b0, acc[mt][nt][1] + b1);
                *(float2*)(C + (size_t)(r0 + g + 8) * Nc + col) =
                    make_float2(acc[mt][nt][2] + b0, acc[mt][nt][3] + b1);
            }
        }
    }
}

// ---------------------------------------------------------------------------
// Flash attention v5: deduplicated smem traffic.
// S-phase: warp (p,s) -> S rows p*16..+16, cols s*32..+32 (as v4).
// Softmax per pair in exp2 domain; P published CTA-wide (64 x 72 bf16).
// PV-phase: warp w -> ALL 64 rows x feats w*64..+64 (each V/P fragment
// loaded once per CTA). Rescale vote-skipped when all c == 1.
// ---------------------------------------------------------------------------
__global__ __launch_bounds__(256, 1) void flash_kernel(
    const __nv_bfloat16* __restrict__ Q, const __nv_bfloat16* __restrict__ K,
    const __nv_bfloat16* __restrict__ V, float* __restrict__ O)
{
    extern __shared__ char sm[];
    const uint32_t smem_u = (uint32_t)__cvta_generic_to_shared(sm);
    const uint32_t qs_u = smem_u + OFF_Q;
    const uint32_t ks_u = smem_u + OFF_K;
    const uint32_t vs_u = smem_u + OFF_V;
    const uint32_t ps_u = smem_u + OFF_P;

    __nv_bfloat16* Pb = (__nv_bfloat16*)(sm + OFF_P);
    float* crow = (float*)(sm + OFF_CROW);
    float* lrow = (float*)(sm + OFF_LR);

    const int tid  = threadIdx.x;
    const int w    = tid >> 5;
    const int lane = tid & 31;
    const int g    = lane >> 2;
    const int t    = lane & 3;
    const int p    = w >> 1;       // pair 0..3
    const int s    = w & 1;        // half 0..1
    const int qb   = blockIdx.x;
    const int barid = p + 1;

    float* mpart = (float*)(sm + OFF_MP + p * 128);
    float* spart = (float*)(sm + OFF_SP + p * 128);

    // ldmatrix lane geometry
    const int a_r   = lane & 15;                         // A-frag row
    const int a_cB  = (lane >> 4) * 16;                  // A-frag 16B col half
    const int k_row = ((lane >> 4) & 1) * 8 + (lane & 7);// K x4: 2 B-frags
    const int k_cB  = ((lane >> 3) & 1) * 16;
    const int v_row = (lane & 7) + ((lane >> 3) & 1) * 8;// V x4 trans: 2 B-frags
    const int v_f   = (lane >> 4) * 8;

    // ---- preloop: stage Q + (K,V) block 0 via cp.async ----
    {
        const int r = tid >> 2, s4 = tid & 3;
        const char* gq = (const char*)(Q + (size_t)(qb * BM + r) * MD + s4 * 32);
        const char* gk = (const char*)(K + (size_t)r * MD + s4 * 32);
#pragma unroll
        for (int e = 0; e < 4; e++) {
            cpa16(qs_u + r * 272 + s4 * 64 + 16 * e, gq + 16 * e);
            cpa16(ks_u + r * 272 + s4 * 64 + 16 * e, gk + 16 * e);
        }
#pragma unroll
        for (int e = 0; e < 16; e++) {
            int f = tid + 256 * e;
            int vr = f >> 6, vc = f & 63;
            cpa16(vs_u + vr * 1040 + vc * 16,
                  (const char*)(V + (size_t)vr * FD) + vc * 16);
        }
        cp_commit();
    }

    float oacc[4][8][4];
#pragma unroll
    for (int mt = 0; mt < 4; mt++)
#pragma unroll
        for (int nt = 0; nt < 8; nt++)
#pragma unroll
            for (int e = 0; e < 4; e++) oacc[mt][nt][e] = 0.f;

    float m_lo = -1e30f, m_hi = -1e30f, l_lo = 0.f, l_hi = 0.f;
    // log2(e) / sqrt(128): softmax runs in exp2 domain
    const float SC = 0.12751744f;

    for (int kb = 0; kb < NKV; kb++) {
        const int cur = kb & 1;
        cp_wait0();
        __syncthreads();   // K/V[kb] ready; P free for overwrite

        // stage next block (full-iteration prefetch window)
        if (kb + 1 < NKV) {
            const int r = tid >> 2, s4 = tid & 3;
            const uint32_t kd = ks_u + (cur ^ 1) * KBUF;
            const uint32_t vd = vs_u + (cur ^ 1) * VBUF;
            const char* gk = (const char*)(K + (size_t)((kb + 1) * BN + r) * MD + s4 * 32);
#pragma unroll
            for (int e = 0; e < 4; e++)
                cpa16(kd + r * 272 + s4 * 64 + 16 * e, gk + 16 * e);
#pragma unroll
            for (int e = 0; e < 16; e++) {
                int f = tid + 256 * e;
                int vr = f >> 6, vc = f & 63;
                cpa16(vd + vr * 1040 + vc * 16,
                      (const char*)(V + (size_t)((kb + 1) * BN + vr) * FD) + vc * 16);
            }
            cp_commit();
        }

        // ---- S = Q @ K^T : rows p*16..+16, cols s*32..+32 ----
        const uint32_t ksm = ks_u + cur * KBUF;
        float sacc[4][4];
#pragma unroll
        for (int nt = 0; nt < 4; nt++)
#pragma unroll
            for (int e = 0; e < 4; e++) sacc[nt][e] = 0.f;

#pragma unroll
        for (int kt = 0; kt < 8; kt++) {
            unsigned aq[4];
            ldsm4(aq, qs_u + (p * 16 + a_r) * 272 + kt * 32 + a_cB);
#pragma unroll
            for (int n2 = 0; n2 < 2; n2++) {
                unsigned bk[4];
                ldsm4(bk, ksm + (s * 32 + n2 * 16 + k_row) * 272 + kt * 32 + k_cB);
                mma16(sacc[n2 * 2],     aq, bk);
                mma16(sacc[n2 * 2 + 1], aq, bk + 2);
            }
        }

        // ---- softmax (exp2 domain) ----
        float mlo = m_lo, mhi = m_hi;
#pragma unroll
        for (int nt = 0; nt < 4; nt++) {
            sacc[nt][0] *= SC; sacc[nt][1] *= SC;
            sacc[nt][2] *= SC; sacc[nt][3] *= SC;
            mlo = fmaxf(mlo, fmaxf(sacc[nt][0], sacc[nt][1]));
            mhi = fmaxf(mhi, fmaxf(sacc[nt][2], sacc[nt][3]));
        }
        mlo = fmaxf(mlo, __shfl_xor_sync(0xffffffffu, mlo, 1));
        mlo = fmaxf(mlo, __shfl_xor_sync(0xffffffffu, mlo, 2));
        mhi = fmaxf(mhi, __shfl_xor_sync(0xffffffffu, mhi, 1));
        mhi = fmaxf(mhi, __shfl_xor_sync(0xffffffffu, mhi, 2));
        if (t == 0) {
            mpart[s * 16 + g]     = mlo;
            mpart[s * 16 + 8 + g] = mhi;
        }
        pair_bar(barid);
        const float mxlo = fmaxf(mlo, mpart[(s ^ 1) * 16 + g]);
        const float mxhi = fmaxf(mhi, mpart[(s ^ 1) * 16 + 8 + g]);
        const float clo = ex2(m_lo - mxlo);
        const float chi = ex2(m_hi - mxhi);

        float slo = 0.f, shi = 0.f;
#pragma unroll
        for (int nt = 0; nt < 4; nt++) {
            float p0 = ex2(sacc[nt][0] - mxlo);
            float p1 = ex2(sacc[nt][1] - mxlo);
            float p2 = ex2(sacc[nt][2] - mxhi);
            float p3 = ex2(sacc[nt][3] - mxhi);
            slo += p0 + p1;
            shi += p2 + p3;
            const int c0 = s * 32 + nt * 8 + 2 * t;
            *(__nv_bfloat162*)(Pb + (p * 16 + g) * 72 + c0) =
                __float22bfloat162_rn(make_float2(p0, p1));
            *(__nv_bfloat162*)(Pb + (p * 16 + 8 + g) * 72 + c0) =
                __float22bfloat162_rn(make_float2(p2, p3));
        }
        slo += __shfl_xor_sync(0xffffffffu, slo, 1);
        slo += __shfl_xor_sync(0xffffffffu, slo, 2);
        shi += __shfl_xor_sync(0xffffffffu, shi, 1);
        shi += __shfl_xor_sync(0xffffffffu, shi, 2);
        if (t == 0) {
            spart[s * 16 + g]     = slo;
            spart[s * 16 + 8 + g] = shi;
        }
        pair_bar(barid);
        l_lo = l_lo * clo + slo + spart[(s ^ 1) * 16 + g];
        l_hi = l_hi * chi + shi + spart[(s ^ 1) * 16 + 8 + g];
        m_lo = mxlo; m_hi = mxhi;
        if (s == 0 && t == 0) {
            crow[p * 16 + g]     = clo;
            crow[p * 16 + 8 + g] = chi;
        }
        __syncthreads();   // publish P(kb) + crow(kb)

        // ---- rescale (vote-skip when all c == 1) ----
        float cr[8];
#pragma unroll
        for (int mt = 0; mt < 4; mt++) {
            cr[2 * mt]     = crow[mt * 16 + g];
            cr[2 * mt + 1] = crow[mt * 16 + 8 + g];
        }
        bool allone = (cr[0] == 1.f) & (cr[1] == 1.f) & (cr[2] == 1.f) & (cr[3] == 1.f)
                    & (cr[4] == 1.f) & (cr[5] == 1.f) & (cr[6] == 1.f) & (cr[7] == 1.f);
        if (!__all_sync(0xffffffffu, allone)) {
#pragma unroll
            for (int mt = 0; mt < 4; mt++)
#pragma unroll
                for (int nt = 0; nt < 8; nt++) {
                    oacc[mt][nt][0] *= cr[2 * mt];     oacc[mt][nt][1] *= cr[2 * mt];
                    oacc[mt][nt][2] *= cr[2 * mt + 1]; oacc[mt][nt][3] *= cr[2 * mt + 1];
                }
        }

        // ---- O += P @ V : all 64 rows x feats w*64..+64 ----
        const uint32_t vsm = vs_u + cur * VBUF;
#pragma unroll
        for (int kt = 0; kt < 4; kt++) {
            unsigned ap[4][4];
#pragma unroll
            for (int mt = 0; mt < 4; mt++)
                ldsm4(ap[mt], ps_u + (mt * 16 + a_r) * 144 + kt * 32 + a_cB);
#pragma unroll
            for (int j = 0; j < 4; j++) {
                unsigned bv[4];
                ldsm4t(bv, vsm + (kt * 16 + v_row) * 1040
                               + (w * 64 + j * 16 + v_f) * 2);
#pragma unroll
                for (int mt = 0; mt < 4; mt++) {
                    mma16(oacc[mt][2 * j],     ap[mt], bv);
                    mma16(oacc[mt][2 * j + 1], ap[mt], bv + 2);
                }
            }
        }
    }

    // ---- Epilogue ----
    if (s == 0 && t == 0) {
        lrow[p * 16 + g]     = l_lo;
        lrow[p * 16 + 8 + g] = l_hi;
    }
    __syncthreads();
#pragma unroll
    for (int mt = 0; mt < 4; mt++) {
        const float inv_lo = 1.f / lrow[mt * 16 + g];
        const float inv_hi = 1.f / lrow[mt * 16 + 8 + g];
#pragma unroll
        for (int nt = 0; nt < 8; nt++) {
            const int col = w * 64 + (nt >> 1) * 16 + (nt & 1) * 8 + 2 * t;
            *(float2*)(O + (size_t)(qb * BM + mt * 16 + g) * FD + col) =
                make_float2(oacc[mt][nt][0] * inv_lo, oacc[mt][nt][1] * inv_lo);
            *(float2*)(O + (size_t)(qb * BM + mt * 16 + 8 + g) * FD + col) =
                make_float2(oacc[mt][nt][2] * inv_hi, oacc[mt][nt][3] * inv_hi);
        }
    }
}

// ---------------------------------------------------------------------------
// kernel_launch
// ---------------------------------------------------------------------------
extern "C" void kernel_launch(void* const* d_in, const int* in_sizes, int n_in,
                              void* d_out, int out_size)
{
    const float* x  = (const float*)d_in[0];
    const float* Wq = (const float*)d_in[1];
    const float* bq = (const float*)d_in[2];
    const float* Wk = (const float*)d_in[3];
    const float* bk = (const float*)d_in[4];
    const float* Wv = (const float*)d_in[5];
    const float* bv = (const float*)d_in[6];
    const float* Wo = (const float*)d_in[7];
    const float* bo = (const float*)d_in[8];
    float* out = (float*)d_out;

    __nv_bfloat16 *pQ, *pK, *pV;
    float* pA;
    cudaGetSymbolAddress((void**)&pQ, g_Qb);
    cudaGetSymbolAddress((void**)&pK, g_Kb);
    cudaGetSymbolAddress((void**)&pV, g_Vb);
    cudaGetSymbolAddress((void**)&pA, g_att);

    cudaFuncSetAttribute(flash_kernel,
                         cudaFuncAttributeMaxDynamicSharedMemorySize, SMEM_TOTAL);

    dim3 blk(256);
    gemm_tf32_kernel<1><<<dim3(1, 128), blk>>>(x, Wq, bq, pQ, FD, MD);
    gemm_tf32_kernel<1><<<dim3(1, 128), blk>>>(x, Wk, bk, pK, FD, MD);
    gemm_tf32_kernel<1><<<dim3(4, 128), blk>>>(x, Wv, bv, pV, FD, FD);
    flash_kernel<<<NPTS / BM, 256, SMEM_TOTAL>>>(pQ, pK, pV, pA);
    gemm_tf32_kernel<0><<<dim3(4, 128), blk>>>(pA, Wo, bo, out, FD, FD);
}

// round 12
// speedup vs baseline: 1.0021x; 1.0021x over previous
#include <cuda_runtime.h>
#include <cuda_bf16.h>
#include <cstdint>

#define NPTS 16384
#define FD   512
#define MD   128
#define BM   64
#define BN   64
#define NKV  (NPTS / BN)

// smem byte offsets (all 16B aligned)
#define OFF_Q    0                 // 64 rows x 272B
#define OFF_K    17408             // 2 buffers x 17408
#define OFF_V    52224             // 2 buffers x 66560
#define OFF_P    185344            // CTA-wide P: 64 rows x 144B = 9216
#define OFF_CROW 194560            // 64 floats
#define OFF_MP   194816            // 4 pairs x 128B
#define OFF_SP   195328            // 4 pairs x 128B
#define OFF_LR   195840            // 64 floats
#define SMEM_TOTAL 196096
#define KBUF 17408
#define VBUF 66560

// Scratch (device globals: allocation-free rule)
__device__ __nv_bfloat16 g_Qb[NPTS * MD];
__device__ __nv_bfloat16 g_Kb[NPTS * MD];
__device__ __nv_bfloat16 g_Vb[NPTS * FD];
__device__ float g_att[NPTS * FD];

// ---------------------------------------------------------------------------
// helpers
// ---------------------------------------------------------------------------
__device__ __forceinline__ float cvt_tf32(float x) {
    unsigned u;
    asm("cvt.rna.tf32.f32 %0, %1;" : "=r"(u) : "f"(x));
    return __uint_as_float(u);
}
__device__ __forceinline__ unsigned fu(float x) { return __float_as_uint(x); }
__device__ __forceinline__ float ex2(float x) {
    float y;
    asm("ex2.approx.f32 %0, %1;" : "=f"(y) : "f"(x));
    return y;
}

__device__ __forceinline__ void ldsm4(unsigned* r, uint32_t a) {
    asm volatile("ldmatrix.sync.aligned.m8n8.x4.shared.b16 {%0,%1,%2,%3}, [%4];"
                 : "=r"(r[0]), "=r"(r[1]), "=r"(r[2]), "=r"(r[3]) : "r"(a));
}
__device__ __forceinline__ void ldsm4t(unsigned* r, uint32_t a) {
    asm volatile("ldmatrix.sync.aligned.m8n8.x4.trans.shared.b16 {%0,%1,%2,%3}, [%4];"
                 : "=r"(r[0]), "=r"(r[1]), "=r"(r[2]), "=r"(r[3]) : "r"(a));
}

// bf16 m16n8k16, fp32 accum
__device__ __forceinline__ void mma16(float* d, const unsigned* a, const unsigned* b) {
    asm volatile(
        "mma.sync.aligned.m16n8k16.row.col.f32.bf16.bf16.f32 "
        "{%0,%1,%2,%3}, {%4,%5,%6,%7}, {%8,%9}, {%0,%1,%2,%3};"
        : "+f"(d[0]), "+f"(d[1]), "+f"(d[2]), "+f"(d[3])
        : "r"(a[0]), "r"(a[1]), "r"(a[2]), "r"(a[3]), "r"(b[0]), "r"(b[1]));
}
// tf32 m16n8k8 (projection GEMMs)
__device__ __forceinline__ void mma8(float* d, const unsigned* a, const unsigned* b) {
    asm volatile(
        "mma.sync.aligned.m16n8k8.row.col.f32.tf32.tf32.f32 "
        "{%0,%1,%2,%3}, {%4,%5,%6,%7}, {%8,%9}, {%0,%1,%2,%3};"
        : "+f"(d[0]), "+f"(d[1]), "+f"(d[2]), "+f"(d[3])
        : "r"(a[0]), "r"(a[1]), "r"(a[2]), "r"(a[3]), "r"(b[0]), "r"(b[1]));
}

__device__ __forceinline__ void cpa16(uint32_t dst, const void* src) {
    asm volatile("cp.async.cg.shared.global [%0], [%1], 16;" :: "r"(dst), "l"(src));
}
__device__ __forceinline__ void cp_commit() {
    asm volatile("cp.async.commit_group;");
}
__device__ __forceinline__ void cp_wait0() {
    asm volatile("cp.async.wait_group 0;");
}
__device__ __forceinline__ void pair_bar(int id) {
    asm volatile("bar.sync %0, 64;" :: "r"(id) : "memory");
}

// ---------------------------------------------------------------------------
// TF32 GEMM: C[128x128 tile] = A @ B + bias. OUT_BF16 selects output type.
// ---------------------------------------------------------------------------
#define AS_STRIDE 36
#define BS_STRIDE 136
template <int OUT_BF16>
__global__ __launch_bounds__(256) void gemm_tf32_kernel(
    const float* __restrict__ A, const float* __restrict__ B,
    const float* __restrict__ bias, void* __restrict__ Cv,
    int Kd, int Nc)
{
    __shared__ float As[128 * AS_STRIDE];
    __shared__ float Bs[32 * BS_STRIDE];

    const int tid  = threadIdx.x;
    const int w    = tid >> 5;
    const int lane = tid & 31;
    const int g    = lane >> 2;
    const int t    = lane & 3;
    const int wm   = w & 3;
    const int wn   = w >> 2;
    const int rowBase = blockIdx.y * 128;
    const int colBase = blockIdx.x * 128;

    float acc[2][8][4];
#pragma unroll
    for (int mt = 0; mt < 2; mt++)
#pragma unroll
        for (int nt = 0; nt < 8; nt++)
#pragma unroll
            for (int e = 0; e < 4; e++) acc[mt][nt][e] = 0.f;

    for (int k0 = 0; k0 < Kd; k0 += 32) {
        float4 areg[4], breg[4];
#pragma unroll
        for (int e = 0; e < 4; e++) {
            int f4 = tid + 256 * e;
            int ar = f4 >> 3, ac4 = f4 & 7;
            areg[e] = *(const float4*)(A + (size_t)(rowBase + ar) * Kd + k0 + ac4 * 4);
            int br = f4 >> 5, bc4 = f4 & 31;
            breg[e] = *(const float4*)(B + (size_t)(k0 + br) * Nc + colBase + bc4 * 4);
        }
        __syncthreads();
#pragma unroll
        for (int e = 0; e < 4; e++) {
            int f4 = tid + 256 * e;
            int ar = f4 >> 3, ac4 = f4 & 7;
            float4 v = areg[e];
            v.x = cvt_tf32(v.x); v.y = cvt_tf32(v.y);
            v.z = cvt_tf32(v.z); v.w = cvt_tf32(v.w);
            *(float4*)(As + ar * AS_STRIDE + ac4 * 4) = v;
            int br = f4 >> 5, bc4 = f4 & 31;
            float4 u = breg[e];
            u.x = cvt_tf32(u.x); u.y = cvt_tf32(u.y);
            u.z = cvt_tf32(u.z); u.w = cvt_tf32(u.w);
            *(float4*)(Bs + br * BS_STRIDE + bc4 * 4) = u;
        }
        __syncthreads();

#pragma unroll
        for (int kt = 0; kt < 4; kt++) {
            unsigned afr[2][4];
#pragma unroll
            for (int mt = 0; mt < 2; mt++) {
                const float* ap = As + (wm * 32 + mt * 16) * AS_STRIDE + kt * 8;
                afr[mt][0] = fu(ap[g * AS_STRIDE + t]);
                afr[mt][1] = fu(ap[(g + 8) * AS_STRIDE + t]);
                afr[mt][2] = fu(ap[g * AS_STRIDE + t + 4]);
                afr[mt][3] = fu(ap[(g + 8) * AS_STRIDE + t + 4]);
            }
#pragma unroll
            for (int nt = 0; nt < 8; nt++) {
                const float* bp = Bs + wn * 64 + nt * 8;
                unsigned bfr[2];
                bfr[0] = fu(bp[(kt * 8 + t) * BS_STRIDE + g]);
                bfr[1] = fu(bp[(kt * 8 + t + 4) * BS_STRIDE + g]);
#pragma unroll
                for (int mt = 0; mt < 2; mt++) mma8(acc[mt][nt], afr[mt], bfr);
            }
        }
    }

#pragma unroll
    for (int mt = 0; mt < 2; mt++) {
        int r0 = rowBase + wm * 32 + mt * 16;
#pragma unroll
        for (int nt = 0; nt < 8; nt++) {
            int col = colBase + wn * 64 + nt * 8 + 2 * t;
            float b0 = bias[col], b1 = bias[col + 1];
            if (OUT_BF16) {
                __nv_bfloat16* C = (__nv_bfloat16*)Cv;
                __nv_bfloat162 lo = __float22bfloat162_rn(
                    make_float2(acc[mt][nt][0] + b0, acc[mt][nt][1] + b1));
                __nv_bfloat162 hi = __float22bfloat162_rn(
                    make_float2(acc[mt][nt][2] + b0, acc[mt][nt][3] + b1));
                *(__nv_bfloat162*)(C + (size_t)(r0 + g)     * Nc + col) = lo;
                *(__nv_bfloat162*)(C + (size_t)(r0 + g + 8) * Nc + col) = hi;
            } else {
                float* C = (float*)Cv;
                *(float2*)(C + (size_t)(r0 + g) * Nc + col) =
                    make_float2(acc[mt][nt][0] + b0, acc[mt][nt][1] + b1);
                *(float2*)(C + (size_t)(r0 + g + 8) * Nc + col) =
                    make_float2(acc[mt][nt][2] + b0, acc[mt][nt][3] + b1);
            }
        }
    }
}

// ---------------------------------------------------------------------------
// Flash attention v6: software-pipelined. Region of iter kb computes
// PV(kb) AND S(kb+1) interleaved (independent MMA chains -> 2x ILP);
// softmax(kb) is the only exposed serial segment.
// Buffers: V(kb+1) staged at iter-kb top into (kb+1)&1; K(kb+2) into kb&1.
// ---------------------------------------------------------------------------
__global__ __launch_bounds__(256, 1) void flash_kernel(
    const __nv_bfloat16* __restrict__ Q, const __nv_bfloat16* __restrict__ K,
    const __nv_bfloat16* __restrict__ V, float* __restrict__ O)
{
    extern __shared__ char sm[];
    const uint32_t smem_u = (uint32_t)__cvta_generic_to_shared(sm);
    const uint32_t qs_u = smem_u + OFF_Q;
    const uint32_t ks_u = smem_u + OFF_K;
    const uint32_t vs_u = smem_u + OFF_V;
    const uint32_t ps_u = smem_u + OFF_P;

    __nv_bfloat16* Pb = (__nv_bfloat16*)(sm + OFF_P);
    float* crow = (float*)(sm + OFF_CROW);
    float* lrow = (float*)(sm + OFF_LR);

    const int tid  = threadIdx.x;
    const int w    = tid >> 5;
    const int lane = tid & 31;
    const int g    = lane >> 2;
    const int t    = lane & 3;
    const int p    = w >> 1;       // pair 0..3
    const int s    = w & 1;        // half 0..1
    const int qb   = blockIdx.x;
    const int barid = p + 1;

    float* mpart = (float*)(sm + OFF_MP + p * 128);
    float* spart = (float*)(sm + OFF_SP + p * 128);

    // ldmatrix lane geometry
    const int a_r   = lane & 15;                         // A-frag row
    const int a_cB  = (lane >> 4) * 16;                  // A-frag 16B col half
    const int k_row = ((lane >> 4) & 1) * 8 + (lane & 7);// K x4: 2 B-frags
    const int k_cB  = ((lane >> 3) & 1) * 16;
    const int v_row = (lane & 7) + ((lane >> 3) & 1) * 8;// V x4 trans: 2 B-frags
    const int v_f   = (lane >> 4) * 8;

    const int r  = tid >> 2;
    const int s4 = tid & 3;

    // ---- prologue: stage Q + K(0) + V(0) ----
    {
        const char* gq = (const char*)(Q + (size_t)(qb * BM + r) * MD + s4 * 32);
        const char* gk = (const char*)(K + (size_t)r * MD + s4 * 32);
#pragma unroll
        for (int e = 0; e < 4; e++) {
            cpa16(qs_u + r * 272 + s4 * 64 + 16 * e, gq + 16 * e);
            cpa16(ks_u + r * 272 + s4 * 64 + 16 * e, gk + 16 * e);
        }
#pragma unroll
        for (int e = 0; e < 16; e++) {
            int f = tid + 256 * e;
            int vr = f >> 6, vc = f & 63;
            cpa16(vs_u + vr * 1040 + vc * 16,
                  (const char*)(V + (size_t)vr * FD) + vc * 16);
        }
        cp_commit();
    }
    cp_wait0();
    __syncthreads();

    // ---- S(0) standalone ----
    float sacc[4][4];
#pragma unroll
    for (int nt = 0; nt < 4; nt++)
#pragma unroll
        for (int e = 0; e < 4; e++) sacc[nt][e] = 0.f;
#pragma unroll
    for (int kt = 0; kt < 8; kt++) {
        unsigned aq[4];
        ldsm4(aq, qs_u + (p * 16 + a_r) * 272 + kt * 32 + a_cB);
#pragma unroll
        for (int n2 = 0; n2 < 2; n2++) {
            unsigned bk[4];
            ldsm4(bk, ks_u + (s * 32 + n2 * 16 + k_row) * 272 + kt * 32 + k_cB);
            mma16(sacc[n2 * 2],     aq, bk);
            mma16(sacc[n2 * 2 + 1], aq, bk + 2);
        }
    }
    // stage K(1) into buf 1
    {
        const char* gk = (const char*)(K + (size_t)(BN + r) * MD + s4 * 32);
#pragma unroll
        for (int e = 0; e < 4; e++)
            cpa16(ks_u + KBUF + r * 272 + s4 * 64 + 16 * e, gk + 16 * e);
        cp_commit();
    }

    float oacc[4][8][4];
#pragma unroll
    for (int mt = 0; mt < 4; mt++)
#pragma unroll
        for (int nt = 0; nt < 8; nt++)
#pragma unroll
            for (int e = 0; e < 4; e++) oacc[mt][nt][e] = 0.f;

    float m_lo = -1e30f, m_hi = -1e30f, l_lo = 0.f, l_hi = 0.f;
    const float SC = 0.12751744f;   // log2(e)/sqrt(128)

    for (int kb = 0; kb < NKV; kb++) {
        const int cur = kb & 1;
        cp_wait0();
        __syncthreads();   // V(kb), K(kb+1) ready; PV(kb-1)/S(kb) reads retired

        // stage V(kb+1) -> buf (kb+1)&1, K(kb+2) -> buf kb&1
        if (kb + 1 < NKV) {
            const uint32_t vd = vs_u + (cur ^ 1) * VBUF;
#pragma unroll
            for (int e = 0; e < 16; e++) {
                int f = tid + 256 * e;
                int vr = f >> 6, vc = f & 63;
                cpa16(vd + vr * 1040 + vc * 16,
                      (const char*)(V + (size_t)((kb + 1) * BN + vr) * FD) + vc * 16);
            }
            if (kb + 2 < NKV) {
                const uint32_t kd = ks_u + cur * KBUF;
                const char* gk = (const char*)(K + (size_t)((kb + 2) * BN + r) * MD + s4 * 32);
#pragma unroll
                for (int e = 0; e < 4; e++)
                    cpa16(kd + r * 272 + s4 * 64 + 16 * e, gk + 16 * e);
            }
            cp_commit();
        }

        // ---- softmax(kb) on sacc (exp2 domain) ----
        float mlo = m_lo, mhi = m_hi;
#pragma unroll
        for (int nt = 0; nt < 4; nt++) {
            sacc[nt][0] *= SC; sacc[nt][1] *= SC;
            sacc[nt][2] *= SC; sacc[nt][3] *= SC;
            mlo = fmaxf(mlo, fmaxf(sacc[nt][0], sacc[nt][1]));
            mhi = fmaxf(mhi, fmaxf(sacc[nt][2], sacc[nt][3]));
        }
        mlo = fmaxf(mlo, __shfl_xor_sync(0xffffffffu, mlo, 1));
        mlo = fmaxf(mlo, __shfl_xor_sync(0xffffffffu, mlo, 2));
        mhi = fmaxf(mhi, __shfl_xor_sync(0xffffffffu, mhi, 1));
        mhi = fmaxf(mhi, __shfl_xor_sync(0xffffffffu, mhi, 2));
        if (t == 0) {
            mpart[s * 16 + g]     = mlo;
            mpart[s * 16 + 8 + g] = mhi;
        }
        pair_bar(barid);
        const float mxlo = fmaxf(mlo, mpart[(s ^ 1) * 16 + g]);
        const float mxhi = fmaxf(mhi, mpart[(s ^ 1) * 16 + 8 + g]);
        const float clo = ex2(m_lo - mxlo);
        const float chi = ex2(m_hi - mxhi);

        float slo = 0.f, shi = 0.f;
#pragma unroll
        for (int nt = 0; nt < 4; nt++) {
            float p0 = ex2(sacc[nt][0] - mxlo);
            float p1 = ex2(sacc[nt][1] - mxlo);
            float p2 = ex2(sacc[nt][2] - mxhi);
            float p3 = ex2(sacc[nt][3] - mxhi);
            slo += p0 + p1;
            shi += p2 + p3;
            const int c0 = s * 32 + nt * 8 + 2 * t;
            *(__nv_bfloat162*)(Pb + (p * 16 + g) * 72 + c0) =
                __float22bfloat162_rn(make_float2(p0, p1));
            *(__nv_bfloat162*)(Pb + (p * 16 + 8 + g) * 72 + c0) =
                __float22bfloat162_rn(make_float2(p2, p3));
        }
        slo += __shfl_xor_sync(0xffffffffu, slo, 1);
        slo += __shfl_xor_sync(0xffffffffu, slo, 2);
        shi += __shfl_xor_sync(0xffffffffu, shi, 1);
        shi += __shfl_xor_sync(0xffffffffu, shi, 2);
        if (t == 0) {
            spart[s * 16 + g]     = slo;
            spart[s * 16 + 8 + g] = shi;
        }
        pair_bar(barid);
        l_lo = l_lo * clo + slo + spart[(s ^ 1) * 16 + g];
        l_hi = l_hi * chi + shi + spart[(s ^ 1) * 16 + 8 + g];
        m_lo = mxlo; m_hi = mxhi;
        if (s == 0 && t == 0) {
            crow[p * 16 + g]     = clo;
            crow[p * 16 + 8 + g] = chi;
        }
        __syncthreads();   // publish P(kb) + crow(kb)

        // ---- rescale (vote-skip when all c == 1) ----
        float cr[8];
#pragma unroll
        for (int mt = 0; mt < 4; mt++) {
            cr[2 * mt]     = crow[mt * 16 + g];
            cr[2 * mt + 1] = crow[mt * 16 + 8 + g];
        }
        bool allone = (cr[0] == 1.f) & (cr[1] == 1.f) & (cr[2] == 1.f) & (cr[3] == 1.f)
                    & (cr[4] == 1.f) & (cr[5] == 1.f) & (cr[6] == 1.f) & (cr[7] == 1.f);
        if (!__all_sync(0xffffffffu, allone)) {
#pragma unroll
            for (int mt = 0; mt < 4; mt++)
#pragma unroll
                for (int nt = 0; nt < 8; nt++) {
                    oacc[mt][nt][0] *= cr[2 * mt];     oacc[mt][nt][1] *= cr[2 * mt];
                    oacc[mt][nt][2] *= cr[2 * mt + 1]; oacc[mt][nt][3] *= cr[2 * mt + 1];
                }
        }

        // ---- merged region: PV(kb) + S(kb+1), independent MMA chains ----
        const uint32_t vsm = vs_u + cur * VBUF;
        const uint32_t ksm = ks_u + (cur ^ 1) * KBUF;
        const bool do_s = (kb + 1 < NKV);
#pragma unroll
        for (int nt = 0; nt < 4; nt++)
#pragma unroll
            for (int e = 0; e < 4; e++) sacc[nt][e] = 0.f;

#pragma unroll
        for (int kt = 0; kt < 4; kt++) {
            unsigned ap[4][4];
#pragma unroll
            for (int mt = 0; mt < 4; mt++)
                ldsm4(ap[mt], ps_u + (mt * 16 + a_r) * 144 + kt * 32 + a_cB);
#pragma unroll
            for (int j = 0; j < 4; j++) {
                unsigned bv[4];
                ldsm4t(bv, vsm + (kt * 16 + v_row) * 1040
                               + (w * 64 + j * 16 + v_f) * 2);
#pragma unroll
                for (int mt = 0; mt < 4; mt++) {
                    mma16(oacc[mt][2 * j],     ap[mt], bv);
                    mma16(oacc[mt][2 * j + 1], ap[mt], bv + 2);
                }
            }
            if (do_s) {
#pragma unroll
                for (int u = 0; u < 2; u++) {
                    const int skt = 2 * kt + u;
                    unsigned aq[4];
                    ldsm4(aq, qs_u + (p * 16 + a_r) * 272 + skt * 32 + a_cB);
#pragma unroll
                    for (int n2 = 0; n2 < 2; n2++) {
                        unsigned bk[4];
                        ldsm4(bk, ksm + (s * 32 + n2 * 16 + k_row) * 272
                                      + skt * 32 + k_cB);
                        mma16(sacc[n2 * 2],     aq, bk);
                        mma16(sacc[n2 * 2 + 1], aq, bk + 2);
                    }
                }
            }
        }
    }

    // ---- Epilogue ----
    if (s == 0 && t == 0) {
        lrow[p * 16 + g]     = l_lo;
        lrow[p * 16 + 8 + g] = l_hi;
    }
    __syncthreads();
#pragma unroll
    for (int mt = 0; mt < 4; mt++) {
        const float inv_lo = 1.f / lrow[mt * 16 + g];
        const float inv_hi = 1.f / lrow[mt * 16 + 8 + g];
#pragma unroll
        for (int nt = 0; nt < 8; nt++) {
            const int col = w * 64 + (nt >> 1) * 16 + (nt & 1) * 8 + 2 * t;
            *(float2*)(O + (size_t)(qb * BM + mt * 16 + g) * FD + col) =
                make_float2(oacc[mt][nt][0] * inv_lo, oacc[mt][nt][1] * inv_lo);
            *(float2*)(O + (size_t)(qb * BM + mt * 16 + 8 + g) * FD + col) =
                make_float2(oacc[mt][nt][2] * inv_hi, oacc[mt][nt][3] * inv_hi);
        }
    }
}

// ---------------------------------------------------------------------------
// kernel_launch
// ---------------------------------------------------------------------------
extern "C" void kernel_launch(void* const* d_in, const int* in_sizes, int n_in,
                              void* d_out, int out_size)
{
    const float* x  = (const float*)d_in[0];
    const float* Wq = (const float*)d_in[1];
    const float* bq = (const float*)d_in[2];
    const float* Wk = (const float*)d_in[3];
    const float* bk = (const float*)d_in[4];
    const float* Wv = (const float*)d_in[5];
    const float* bv = (const float*)d_in[6];
    const float* Wo = (const float*)d_in[7];
    const float* bo = (const float*)d_in[8];
    float* out = (float*)d_out;

    __nv_bfloat16 *pQ, *pK, *pV;
    float* pA;
    cudaGetSymbolAddress((void**)&pQ, g_Qb);
    cudaGetSymbolAddress((void**)&pK, g_Kb);
    cudaGetSymbolAddress((void**)&pV, g_Vb);
    cudaGetSymbolAddress((void**)&pA, g_att);

    cudaFuncSetAttribute(flash_kernel,
                         cudaFuncAttributeMaxDynamicSharedMemorySize, SMEM_TOTAL);

    dim3 blk(256);
    gemm_tf32_kernel<1><<<dim3(1, 128), blk>>>(x, Wq, bq, pQ, FD, MD);
    gemm_tf32_kernel<1><<<dim3(1, 128), blk>>>(x, Wk, bk, pK, FD, MD);
    gemm_tf32_kernel<1><<<dim3(4, 128), blk>>>(x, Wv, bv, pV, FD, FD);
    flash_kernel<<<NPTS / BM, 256, SMEM_TOTAL>>>(pQ, pK, pV, pA);
    gemm_tf32_kernel<0><<<dim3(4, 128), blk>>>(pA, Wo, bo, out, FD, FD);
}